// round 14
// baseline (speedup 1.0000x reference)
#include <cuda_runtime.h>

// QuantumConvLayer: probs = [c^4, c^2 s^2, s^4, s^2 c^2],
// c^2 = (1+cos x)/2, s^2 = (1-cos x)/2, x = inputs[i,0].
// HBM-bound streaming: 256MB read + 256MB write (mandatory; spec bound 64us).
// R13: isolate RPT=8 WITHOUT the .cs hints it was confounded with in R3
// (R8 showed hints alone cost ~4%). 8 front-batched dense LDG.128 reads then
// 8 dense STG.128 writes per thread -> 4KB same-direction bursts per warp,
// fewer DRAM read/write turnarounds.

#define RPT 8
#define TPB 256
#define ROWS_PER_BLOCK (RPT * TPB)   // 2048

__device__ __forceinline__ float4 qprobs(float x)
{
    float cx = __cosf(x);
    float c2 = 0.5f + 0.5f * cx;   // cos^2(x/2)
    float s2 = 0.5f - 0.5f * cx;   // sin^2(x/2)
    float cs = c2 * s2;
    return make_float4(c2 * c2, cs, s2 * s2, cs);
}

__global__ void __launch_bounds__(TPB) qconv_kernel(
    const float4* __restrict__ in,  // [N] rows, 16B each; only .x (col 0) used
    float4* __restrict__ out,       // [N]
    int n)
{
    int tile = blockIdx.x * ROWS_PER_BLOCK;
    int t = threadIdx.x;

    if (tile + ROWS_PER_BLOCK <= n) {
        // Fast path (always taken for N = 16M): 8 front-batched dense loads,
        // then 8 dense stores — long same-direction DRAM bursts.
        float x[RPT];
#pragma unroll
        for (int k = 0; k < RPT; k++)
            x[k] = __ldg(in + (tile + t + TPB * k)).x;
#pragma unroll
        for (int k = 0; k < RPT; k++)
            out[tile + t + TPB * k] = qprobs(x[k]);
    } else {
#pragma unroll
        for (int k = 0; k < RPT; k++) {
            int row = tile + t + TPB * k;
            if (row < n)
                out[row] = qprobs(__ldg(in + row).x);
        }
    }
}

extern "C" void kernel_launch(void* const* d_in, const int* in_sizes, int n_in,
                              void* d_out, int out_size)
{
    const float4* in = (const float4*)d_in[0];
    float4* out = (float4*)d_out;
    int n = in_sizes[0] / 4;   // rows

    int grid = (n + ROWS_PER_BLOCK - 1) / ROWS_PER_BLOCK;
    qconv_kernel<<<grid, TPB>>>(in, out, n);
}

// round 16
// speedup vs baseline: 1.0027x; 1.0027x over previous
#include <cuda_runtime.h>

// QuantumConvLayer: probs = [c^4, c^2 s^2, s^4, s^2 c^2],
// c^2 = (1+cos x)/2, s^2 = (1-cos x)/2, x = inputs[i,0].
// HBM-bound streaming: 256MB read + 256MB write (both mandatory, 512MB;
// spec-BW lower bound 64us).
// FINAL (= R5 config): kernel 73.7-74.6us @ 6.45-6.53TB/s (81-82% of spec),
// reproduced 6x, rel_err 1.45e-7.
// Fully-isolated lever ledger:
//   RPT: 1 < 4 > 8 (R13 isolated RPT=8 sans hints: 77.5us, DRAM 78.3%)
//   TPB: 256 > 512 (R11)
//   __cosf half-angle identity: win (R2)
//   dense LDG.128 row reads: win (R5); paired-row 32B/lane: regress (R6)
//   flat grid > persistent single-wave (R4)
//   default cache policy > .cs streaming hints (R8: L1 40->65%, DRAM -4%)
// Remaining gap to spec BW = DRAM read/write turnaround; not program-visible.

#define RPT 4
#define TPB 256
#define ROWS_PER_BLOCK (RPT * TPB)   // 1024

__device__ __forceinline__ float4 qprobs(float x)
{
    float cx = __cosf(x);
    float c2 = 0.5f + 0.5f * cx;   // cos^2(x/2)
    float s2 = 0.5f - 0.5f * cx;   // sin^2(x/2)
    float cs = c2 * s2;
    return make_float4(c2 * c2, cs, s2 * s2, cs);
}

__global__ void __launch_bounds__(TPB) qconv_kernel(
    const float4* __restrict__ in,  // [N] rows, 16B each; only .x (col 0) used
    float4* __restrict__ out,       // [N]
    int n)
{
    int tile = blockIdx.x * ROWS_PER_BLOCK;
    int t = threadIdx.x;

    float x[RPT];
    int row[RPT];

    // Front-batch 4 independent dense LDG.128s (warp = 512B contiguous each)
#pragma unroll
    for (int k = 0; k < RPT; k++) {
        row[k] = tile + t + TPB * k;
        x[k] = (row[k] < n) ? __ldg(in + row[k]).x : 0.0f;
    }

#pragma unroll
    for (int k = 0; k < RPT; k++) {
        if (row[k] < n)
            out[row[k]] = qprobs(x[k]);
    }
}

extern "C" void kernel_launch(void* const* d_in, const int* in_sizes, int n_in,
                              void* d_out, int out_size)
{
    const float4* in = (const float4*)d_in[0];
    float4* out = (float4*)d_out;
    int n = in_sizes[0] / 4;   // rows

    int grid = (n + ROWS_PER_BLOCK - 1) / ROWS_PER_BLOCK;
    qconv_kernel<<<grid, TPB>>>(in, out, n);
}